// round 12
// baseline (speedup 1.0000x reference)
#include <cuda_runtime.h>
#include <cstdint>
#include <cstddef>

#define T_STEPS 2048
#define H_DIM   512
#define B_DIM   32
#define D_IN    128
#define ALPHA   0.1f
#define FIXSCALE 8388608.0f          // 2^23
#define INV_FIXSCALE (1.0f / 8388608.0f)

// ---------------------------------------------------------------------------
// Kernel 1: x_proj GEMM.  C[M,N] = A[M,K] * B[N,K]^T   (at fp32 FFMA roofline)
// ---------------------------------------------------------------------------
__global__ __launch_bounds__(256) void xproj_gemm(const float* __restrict__ A,
                                                  const float* __restrict__ B,
                                                  float* __restrict__ C) {
    __shared__ float As[8][128];
    __shared__ float Bs[8][128];

    const int tid = threadIdx.x;
    const int bm  = blockIdx.x * 128;
    const int bn  = blockIdx.y * 128;

    const int lr = tid >> 1;
    const int lc = (tid & 1) * 4;
    const float* Ap = A + (size_t)(bm + lr) * D_IN + lc;
    const float* Bp = B + (size_t)(bn + lr) * D_IN + lc;

    const int tx = (tid & 15) * 8;
    const int ty = (tid >> 4) * 8;

    float acc[8][8] = {};

    for (int k0 = 0; k0 < D_IN; k0 += 8) {
        const float4 av = *(const float4*)(Ap + k0);
        const float4 bv = *(const float4*)(Bp + k0);
        __syncthreads();
        As[lc + 0][lr] = av.x; As[lc + 1][lr] = av.y;
        As[lc + 2][lr] = av.z; As[lc + 3][lr] = av.w;
        Bs[lc + 0][lr] = bv.x; Bs[lc + 1][lr] = bv.y;
        Bs[lc + 2][lr] = bv.z; Bs[lc + 3][lr] = bv.w;
        __syncthreads();

        #pragma unroll
        for (int k = 0; k < 8; k++) {
            float a[8], bb[8];
            *(float4*)&a[0]  = *(const float4*)&As[k][ty];
            *(float4*)&a[4]  = *(const float4*)&As[k][ty + 4];
            *(float4*)&bb[0] = *(const float4*)&Bs[k][tx];
            *(float4*)&bb[4] = *(const float4*)&Bs[k][tx + 4];
            #pragma unroll
            for (int i = 0; i < 8; i++)
                #pragma unroll
                for (int j = 0; j < 8; j++)
                    acc[i][j] = fmaf(a[i], bb[j], acc[i][j]);
        }
    }

    #pragma unroll
    for (int i = 0; i < 8; i++) {
        float* Cp = C + (size_t)(bm + ty + i) * H_DIM + bn + tx;
        *(float4*)(Cp)     = make_float4(acc[i][0], acc[i][1], acc[i][2], acc[i][3]);
        *(float4*)(Cp + 4) = make_float4(acc[i][4], acc[i][5], acc[i][6], acc[i][7]);
    }
}

// ---------------------------------------------------------------------------
// warp-wide s32 sum (Ampere+ REDUX, definitely on sm_103)
// ---------------------------------------------------------------------------
__device__ __forceinline__ int warp_redux_s32(int v) {
    int r;
    asm("redux.sync.add.s32 %0, %1, 0xffffffff;" : "=r"(r) : "r"(v));
    return r;
}

// single-transaction 64-bit volatile smem access (untearable post)
__device__ __forceinline__ void mb_store(uint32_t addr, int x, int y) {
    asm volatile("st.volatile.shared.v2.u32 [%0], {%1, %2};"
                 :: "r"(addr), "r"(x), "r"(y) : "memory");
}
__device__ __forceinline__ void mb_load(uint32_t addr, int& x, int& y) {
    asm volatile("ld.volatile.shared.v2.u32 {%0, %1}, [%2];"
                 : "=r"(x), "=r"(y) : "r"(addr) : "memory");
}

// ---------------------------------------------------------------------------
// Kernel 2: sequential scan. 4 warps per batch, 4 h per thread.
// BARRIER-FREE dataflow: per step each warp REDUXes its rank-2 partial to
// fixed point (2^23), lane0 posts an int2 into a depth-4 smem ring slot
// [t&3][wid] with a 1-bit round tag ((t>>2)&1) in p0's LSB; all warps
// spin-read the 4 slots and proceed the instant the last one lands.
// Max inter-warp skew is 1 step (every warp consumes every partial every
// step), so the depth-4 ring + 1-bit tag is race-free.
// Fixed-point noise: <= 6 ulp(2^-23) on s -> ~1e-8 on h. Negligible.
// ---------------------------------------------------------------------------
__global__ __launch_bounds__(128) void rnn_scan(const float* __restrict__ m,
                                                const float* __restrict__ n,
                                                float* __restrict__ out) {
    const int b    = blockIdx.x;
    const int tid  = threadIdx.x;
    const int lane = tid & 31;
    const int wid  = tid >> 5;
    const float OMA = 1.0f - ALPHA;

    __shared__ __align__(16) int2 slot[4][4];   // [ring = t&3][warp]

    // init: tag bit (LSB of x) = 1, first expected tag (round 0) = 0
    if (tid < 16) slot[tid >> 2][tid & 3] = make_int2(1, 1);
    __syncthreads();   // once, outside the loop

    // per-h constants (h = tid*4 + k); 2^-23 folded into am
    float n0[4], n1[4], am0[4], am1[4];
    {
        const float4 na = *(const float4*)(n + 8 * tid);
        const float4 nb = *(const float4*)(n + 8 * tid + 4);
        n0[0] = na.x; n1[0] = na.y; n0[1] = na.z; n1[1] = na.w;
        n0[2] = nb.x; n1[2] = nb.y; n0[3] = nb.z; n1[3] = nb.w;
        const float4 ma = *(const float4*)(m + 8 * tid);
        const float4 mb = *(const float4*)(m + 8 * tid + 4);
        const float s = ALPHA * INV_FIXSCALE;
        am0[0] = s * ma.x; am1[0] = s * ma.y;
        am0[1] = s * ma.z; am1[1] = s * ma.w;
        am0[2] = s * mb.x; am1[2] = s * mb.y;
        am0[3] = s * mb.z; am1[3] = s * mb.w;
    }

    const uint32_t slot_base = (uint32_t)__cvta_generic_to_shared(&slot[0][0]);

    float* base = out + (size_t)b * T_STEPS * H_DIM + tid * 4;

    float hs[4] = {0.0f, 0.0f, 0.0f, 0.0f};

    // depth-8 prefetch of x_proj rows
    float4 xp[8];
    #pragma unroll
    for (int d = 0; d < 8; d++) xp[d] = *(const float4*)(base + (size_t)d * H_DIM);

    #pragma unroll 1
    for (int t = 0; t < T_STEPS; t += 4) {
        #pragma unroll
        for (int u = 0; u < 4; u++) {
            const int tt  = t + u;
            const int tag = (tt >> 2) & 1;
            const uint32_t ring = slot_base + (uint32_t)(tt & 3) * 32;
            const float4 x4 = xp[u & 7];   // u indexes within unroll; see reload below

            float th[4];
            #pragma unroll
            for (int k = 0; k < 4; k++)
                asm("tanh.approx.f32 %0, %1;" : "=f"(th[k]) : "f"(hs[k]));

            // rank-2 partial products (shallow trees)
            float p0 = fmaf(th[1], n0[1], th[0] * n0[0]) +
                       fmaf(th[3], n0[3], th[2] * n0[2]);
            float p1 = fmaf(th[1], n1[1], th[0] * n1[0]) +
                       fmaf(th[3], n1[3], th[2] * n1[2]);

            // v = OMA*h + ALPHA*xp  (independent; overlaps the reduction)
            float v[4];
            v[0] = fmaf(ALPHA, x4.x, OMA * hs[0]);
            v[1] = fmaf(ALPHA, x4.y, OMA * hs[1]);
            v[2] = fmaf(ALPHA, x4.z, OMA * hs[2]);
            v[3] = fmaf(ALPHA, x4.w, OMA * hs[3]);

            // fixed-point, warp-collective sum (one REDUX per component)
            int i0 = warp_redux_s32(__float2int_rn(p0 * FIXSCALE));
            int i1 = warp_redux_s32(__float2int_rn(p1 * FIXSCALE));

            // post this warp's partial (tag in LSB of x)
            if (lane == 0)
                mb_store(ring + (uint32_t)wid * 8, (i0 & ~1) | tag, i1);

            // prefetch row tt+8 while waiting (off-chain)
            if (tt + 8 < T_STEPS)
                xp[u & 7] = *(const float4*)(base + (size_t)(tt + 8) * H_DIM);

            // spin until all 4 partials for step tt are posted
            int a0, a1, b0x, b1y, c0, c1, d0, d1;
            for (;;) {
                mb_load(ring +  0, a0,  a1);
                mb_load(ring +  8, b0x, b1y);
                mb_load(ring + 16, c0,  c1);
                mb_load(ring + 24, d0,  d1);
                const int bad = ((a0 ^ tag) | (b0x ^ tag) | (c0 ^ tag) | (d0 ^ tag)) & 1;
                if (!bad) break;
            }

            // exact integer combine, single convert (scale folded into am)
            const float s0 = (float)((a0 + b0x) + (c0 + d0));
            const float s1 = (float)((a1 + b1y) + (c1 + d1));

            // state update + store
            float4 o4;
            hs[0] = fmaf(am0[0], s0, fmaf(am1[0], s1, v[0])); o4.x = hs[0];
            hs[1] = fmaf(am0[1], s0, fmaf(am1[1], s1, v[1])); o4.y = hs[1];
            hs[2] = fmaf(am0[2], s0, fmaf(am1[2], s1, v[2])); o4.z = hs[2];
            hs[3] = fmaf(am0[3], s0, fmaf(am1[3], s1, v[3])); o4.w = hs[3];
            *(float4*)(base + (size_t)tt * H_DIM) = o4;
        }

        // rotate prefetch ring: entries u=0..3 were refilled with rows t+8..t+11;
        // entries 4..7 hold rows t+4..t+7 (to be consumed next outer iter).
        // Swap halves so "u & 7" indexing stays consistent.
        #pragma unroll
        for (int k = 0; k < 4; k++) {
            const float4 tmp = xp[k];
            xp[k] = xp[k + 4];
            xp[k + 4] = tmp;
        }
    }
}

// ---------------------------------------------------------------------------
extern "C" void kernel_launch(void* const* d_in, const int* in_sizes, int n_in,
                              void* d_out, int out_size) {
    const float* x = (const float*)d_in[0];   // [32, 2048, 128]
    const float* m = (const float*)d_in[1];   // [512, 2]
    const float* n = (const float*)d_in[2];   // [512, 2]
    const float* I = (const float*)d_in[3];   // [512, 128]
    float* out = (float*)d_out;               // [32, 2048, 512]

    (void)in_sizes; (void)n_in; (void)out_size;

    dim3 ggrid((B_DIM * T_STEPS) / 128, H_DIM / 128);
    xproj_gemm<<<ggrid, 256>>>(x, I, out);
    rnn_scan<<<B_DIM, 128>>>(m, n, out);
}

// round 13
// speedup vs baseline: 2.3310x; 2.3310x over previous
#include <cuda_runtime.h>
#include <cstdint>
#include <cstddef>

#define T_STEPS 2048
#define H_DIM   512
#define B_DIM   32
#define D_IN    128
#define ALPHA   0.1f

// progress flags: done_flags[b*16 + tchunk] counts finished col-tiles (of 4)
__device__ int done_flags[B_DIM * 16];

__global__ void flags_zero() { done_flags[threadIdx.x] = 0; }

// ---------------------------------------------------------------------------
__device__ __forceinline__ int ld_acquire(const int* p) {
    int v;
    asm volatile("ld.acquire.gpu.global.b32 %0, [%1];" : "=r"(v) : "l"(p));
    return v;
}

__device__ __forceinline__ void wait_chunk(const int* p) {
    while (ld_acquire(p) < 4) __nanosleep(60);
}

__device__ __forceinline__ unsigned long long f2add(unsigned long long a,
                                                    unsigned long long b) {
    unsigned long long r;
    asm("add.rn.f32x2 %0, %1, %2;" : "=l"(r) : "l"(a), "l"(b));
    return r;
}

// ---------------------------------------------------------------------------
// Fused kernel.
//   bid 0..31      : scanner for batch b=bid (threads 0..127; 128..255 exit)
//   bid 32..2079   : one 128x128 GEMM tile of x_proj = x @ I^T, ordered
//                    t-chunk-major so early timesteps finish first.
// ---------------------------------------------------------------------------
__global__ __launch_bounds__(256) void fused(const float* __restrict__ x,
                                             const float* __restrict__ m,
                                             const float* __restrict__ n,
                                             const float* __restrict__ I,
                                             float* __restrict__ out) {
    __shared__ __align__(16) float pool[2048];   // 8 KB: gemm As/Bs | scan part
    const int bid = blockIdx.x;

    if (bid >= B_DIM) {
        // ================= GEMM role =================
        // tile id ordered: tc-major, then batch, then col-tile
        const int g   = bid - B_DIM;
        const int tc  = g >> 7;          // t-chunk 0..15
        const int rem = g & 127;
        const int bb  = rem >> 2;        // batch 0..31
        const int bn4 = rem & 3;         // col tile 0..3
        const int row0 = bb * T_STEPS + tc * 128;   // global M row base
        const int col0 = bn4 * 128;

        float (*As)[128] = (float(*)[128])(pool);          // [8][128]
        float (*Bs)[128] = (float(*)[128])(pool + 1024);   // [8][128]

        const int tid = threadIdx.x;
        const int lr = tid >> 1;
        const int lc = (tid & 1) * 4;
        const float* Ap = x + (size_t)(row0 + lr) * D_IN + lc;
        const float* Bp = I + (size_t)(col0 + lr) * D_IN + lc;

        const int tx = (tid & 15) * 8;
        const int ty = (tid >> 4) * 8;

        float acc[8][8] = {};

        for (int k0 = 0; k0 < D_IN; k0 += 8) {
            const float4 av = *(const float4*)(Ap + k0);
            const float4 bv = *(const float4*)(Bp + k0);
            __syncthreads();
            As[lc + 0][lr] = av.x; As[lc + 1][lr] = av.y;
            As[lc + 2][lr] = av.z; As[lc + 3][lr] = av.w;
            Bs[lc + 0][lr] = bv.x; Bs[lc + 1][lr] = bv.y;
            Bs[lc + 2][lr] = bv.z; Bs[lc + 3][lr] = bv.w;
            __syncthreads();

            #pragma unroll
            for (int k = 0; k < 8; k++) {
                float a[8], bb2[8];
                *(float4*)&a[0]   = *(const float4*)&As[k][ty];
                *(float4*)&a[4]   = *(const float4*)&As[k][ty + 4];
                *(float4*)&bb2[0] = *(const float4*)&Bs[k][tx];
                *(float4*)&bb2[4] = *(const float4*)&Bs[k][tx + 4];
                #pragma unroll
                for (int i = 0; i < 8; i++)
                    #pragma unroll
                    for (int j = 0; j < 8; j++)
                        acc[i][j] = fmaf(a[i], bb2[j], acc[i][j]);
            }
        }

        #pragma unroll
        for (int i = 0; i < 8; i++) {
            float* Cp = out + (size_t)(row0 + ty + i) * H_DIM + col0 + tx;
            *(float4*)(Cp)     = make_float4(acc[i][0], acc[i][1], acc[i][2], acc[i][3]);
            *(float4*)(Cp + 4) = make_float4(acc[i][4], acc[i][5], acc[i][6], acc[i][7]);
        }

        __syncthreads();                 // all tile stores issued
        if (tid == 0) {
            __threadfence();             // release
            atomicAdd(&done_flags[bb * 16 + tc], 1);
        }
        return;
    }

    // ================= scanner role (R3 structure) =================
    if (threadIdx.x >= 128) return;      // named barrier covers 128 threads

    const int b    = bid;
    const int tid  = threadIdx.x;
    const int lane = tid & 31;
    const int wid  = tid >> 5;
    const float OMA = 1.0f - ALPHA;

    float2 (*part)[16] = (float2(*)[16])(pool);   // [2][16]

    // per-h constants (h = tid*4 + k)
    float n0[4], n1[4], am0[4], am1[4];
    {
        const float4 na = *(const float4*)(n + 8 * tid);
        const float4 nb = *(const float4*)(n + 8 * tid + 4);
        n0[0] = na.x; n1[0] = na.y; n0[1] = na.z; n1[1] = na.w;
        n0[2] = nb.x; n1[2] = nb.y; n0[3] = nb.z; n1[3] = nb.w;
        const float4 ma = *(const float4*)(m + 8 * tid);
        const float4 mb = *(const float4*)(m + 8 * tid + 4);
        am0[0] = ALPHA * ma.x; am1[0] = ALPHA * ma.y;
        am0[1] = ALPHA * ma.z; am1[1] = ALPHA * ma.w;
        am0[2] = ALPHA * mb.x; am1[2] = ALPHA * mb.y;
        am0[3] = ALPHA * mb.z; am1[3] = ALPHA * mb.w;
    }

    float* base = out + (size_t)b * T_STEPS * H_DIM + tid * 4;

    float hs[4] = {0.0f, 0.0f, 0.0f, 0.0f};

    // gate: chunks 0 and 1 must be produced before prefetching rows 0..3
    wait_chunk(&done_flags[b * 16 + 0]);
    wait_chunk(&done_flags[b * 16 + 1]);

    float4 xp[4];
    #pragma unroll
    for (int d = 0; d < 4; d++) xp[d] = *(const float4*)(base + (size_t)d * H_DIM);

    #pragma unroll 1
    for (int t = 0; t < T_STEPS; t += 4) {
        // at each 128-step chunk boundary, ensure chunk c+1 is produced
        // (covers prefetch lookahead of 4 into the next chunk)
        if ((t & 127) == 0 && t > 0) {
            int c1 = (t >> 7) + 1;
            if (c1 > 15) c1 = 15;
            wait_chunk(&done_flags[b * 16 + c1]);
        }

        #pragma unroll
        for (int u = 0; u < 4; u++) {
            const int tt = t + u;
            const float4 x4 = xp[u];

            float th[4];
            #pragma unroll
            for (int k = 0; k < 4; k++)
                asm("tanh.approx.f32 %0, %1;" : "=f"(th[k]) : "f"(hs[k]));

            float p0 = fmaf(th[1], n0[1], th[0] * n0[0]) +
                       fmaf(th[3], n0[3], th[2] * n0[2]);
            float p1 = fmaf(th[1], n1[1], th[0] * n1[0]) +
                       fmaf(th[3], n1[3], th[2] * n1[2]);

            float v[4];
            v[0] = fmaf(ALPHA, x4.x, OMA * hs[0]);
            v[1] = fmaf(ALPHA, x4.y, OMA * hs[1]);
            v[2] = fmaf(ALPHA, x4.z, OMA * hs[2]);
            v[3] = fmaf(ALPHA, x4.w, OMA * hs[3]);

            // 3-level butterfly: lanes 0-3 hold coset partials
            #pragma unroll
            for (int o = 16; o >= 4; o >>= 1) {
                p0 += __shfl_xor_sync(0xffffffffu, p0, o);
                p1 += __shfl_xor_sync(0xffffffffu, p1, o);
            }

            const int par = tt & 1;
            if (lane < 4) part[par][wid * 4 + lane] = make_float2(p0, p1);
            asm volatile("bar.sync 1, 128;" ::: "memory");

            if (tt + 4 < T_STEPS)
                xp[u] = *(const float4*)(base + (size_t)(tt + 4) * H_DIM);

            // gather 16 float2 partials with packed f32x2 adds
            const ulonglong2* pp = (const ulonglong2*)&part[par][0];
            unsigned long long r[8];
            #pragma unroll
            for (int w = 0; w < 8; w++) {
                const ulonglong2 q = pp[w];
                r[w] = f2add(q.x, q.y);
            }
            r[0] = f2add(r[0], r[1]); r[2] = f2add(r[2], r[3]);
            r[4] = f2add(r[4], r[5]); r[6] = f2add(r[6], r[7]);
            r[0] = f2add(r[0], r[2]); r[4] = f2add(r[4], r[6]);
            r[0] = f2add(r[0], r[4]);

            float s0, s1;
            asm("mov.b64 {%0, %1}, %2;" : "=f"(s0), "=f"(s1) : "l"(r[0]));

            float4 o4;
            hs[0] = fmaf(am0[0], s0, fmaf(am1[0], s1, v[0])); o4.x = hs[0];
            hs[1] = fmaf(am0[1], s0, fmaf(am1[1], s1, v[1])); o4.y = hs[1];
            hs[2] = fmaf(am0[2], s0, fmaf(am1[2], s1, v[2])); o4.z = hs[2];
            hs[3] = fmaf(am0[3], s0, fmaf(am1[3], s1, v[3])); o4.w = hs[3];
            *(float4*)(base + (size_t)tt * H_DIM) = o4;
        }
    }
}

// ---------------------------------------------------------------------------
extern "C" void kernel_launch(void* const* d_in, const int* in_sizes, int n_in,
                              void* d_out, int out_size) {
    const float* x = (const float*)d_in[0];   // [32, 2048, 128]
    const float* m = (const float*)d_in[1];   // [512, 2]
    const float* n = (const float*)d_in[2];   // [512, 2]
    const float* I = (const float*)d_in[3];   // [512, 128]
    float* out = (float*)d_out;               // [32, 2048, 512]

    (void)in_sizes; (void)n_in; (void)out_size;

    flags_zero<<<1, B_DIM * 16>>>();
    fused<<<B_DIM + (B_DIM * T_STEPS / 128) * (H_DIM / 128), 256>>>(x, m, n, I, out);
}